// round 13
// baseline (speedup 1.0000x reference)
#include <cuda_runtime.h>
#include <cuda_fp16.h>

#define HH 128
#define WW 128
#define CC 256
#define BB 4
#define NROI 512
#define NSL 4     // row-slice blocks per ROI
#define UB  6     // pixel batch (loads in flight per thread)

// 32 MB fp16 NHWC scratch + 2 MB partial-sum buffer (static device globals)
__device__ __half g_nhwc_h[(size_t)BB * HH * WW * CC];
__device__ float  g_part[(size_t)NROI * NSL * CC];

// ---------------------------------------------------------------------------
// Kernel 1 (v4): NCHW fp32 -> NHWC fp16 transpose, front-batched loads.
// Tile: 128 pixels x 64 channels. Each thread: ALL 8 float4 loads (4 channel
// pairs x 2 planes) issued back-to-back into registers (__ldcs streaming),
// THEN convert + STS. 4 KB/warp in flight -> DRAM latency fully covered.
// Write phase unchanged: lane l stores channel pair l -> 128 B sector STG.
// ---------------------------------------------------------------------------
__global__ __launch_bounds__(256) void nchw_to_nhwc_h4(const float* __restrict__ in) {
    __shared__ unsigned int stile[32][129];  // [channel pair][pixel 0..127]
    const int b  = blockIdx.z;
    const int p0 = blockIdx.x * 128;         // pixel tile base (HW dim)
    const int c0 = blockIdx.y * 64;          // channel tile base (64 channels)
    const int tx = threadIdx.x & 31;
    const int ty = threadIdx.x >> 5;         // 0..7

    const size_t bOff = (size_t)b * CC * (HH * WW);
    const float* pbase = in + bOff + p0;

    float4 va[4], vb[4];
#pragma unroll
    for (int k = 0; k < 4; k++) {
        const int i = ty + 8 * k;            // channel pair 0..31
        va[k] = __ldcs((const float4*)(pbase + (size_t)(c0 + 2 * i)     * (HH * WW)) + tx);
        vb[k] = __ldcs((const float4*)(pbase + (size_t)(c0 + 2 * i + 1) * (HH * WW)) + tx);
    }
#pragma unroll
    for (int k = 0; k < 4; k++) {
        const int i = ty + 8 * k;
        const __half2 h0 = __floats2half2_rn(va[k].x, vb[k].x);
        const __half2 h1 = __floats2half2_rn(va[k].y, vb[k].y);
        const __half2 h2 = __floats2half2_rn(va[k].z, vb[k].z);
        const __half2 h3 = __floats2half2_rn(va[k].w, vb[k].w);
        stile[i][4 * tx + 0] = *(const unsigned int*)&h0;
        stile[i][4 * tx + 1] = *(const unsigned int*)&h1;
        stile[i][4 * tx + 2] = *(const unsigned int*)&h2;
        stile[i][4 * tx + 3] = *(const unsigned int*)&h3;
    }
    __syncthreads();

    unsigned int* dstbase = (unsigned int*)g_nhwc_h + ((size_t)b * (HH * WW)) * (CC / 2) + (c0 >> 1);
#pragma unroll
    for (int j = 0; j < 16; j++) {
        const int p = ty * 16 + j;           // pixel within tile 0..127
        dstbase[(size_t)(p0 + p) * (CC / 2) + tx] = stile[tx][p];
    }
}

// ---------------------------------------------------------------------------
// Kernel 2: block (roi, s). Footprint (nr x nc) flattened to npx pixels; 32
// contiguous balanced ranges over 4 blocks x 8 warps. Lanes carry 8 channels
// (uint4). UB independent loads in flight; 64-reg budget.
// (unchanged from R12: measured ~25.0us)
// ---------------------------------------------------------------------------
__global__ __launch_bounds__(256, 4) void roi_partial_kernel(const float* __restrict__ rois) {
    const int roi  = blockIdx.x;
    const int s    = blockIdx.y;     // 0..3
    const int t    = threadIdx.x;
    const int lane = t & 31;
    const int wrp  = t >> 5;         // 0..7

    __shared__ int   s_rows[32];
    __shared__ float s_rw[32];
    __shared__ int   s_cols[32];
    __shared__ float s_cw[32];
    __shared__ int   s_cnt[2];
    __shared__ int   s_warpoff[8];
    __shared__ float s_red[8][CC];   // 8 KB

    // --- ROI params (every thread; same FP ops as reference) ----------------
    const float* R = rois + roi * 6;
    const int   b   = (int)R[0];
    const float cx  = R[2], cy = R[3], rw_ = R[4], rh_ = R[5];
    const float x1f = __half2float(__float2half_rn((cx - 0.5f * rw_) * 128.0f));
    const float y1f = __half2float(__float2half_rn((cy - 0.5f * rh_) * 128.0f));
    const float x2f = __half2float(__float2half_rn((cx + 0.5f * rw_) * 128.0f));
    const float y2f = __half2float(__float2half_rn((cy + 0.5f * rh_) * 128.0f));
    const float roi_w = fmaxf(x2f - x1f, 1.0f);
    const float roi_h = fmaxf(y2f - y1f, 1.0f);

    // --- Per-thread axis weight: threads 0-127 -> rows, 128-255 -> cols -----
    {
        const int   axis  = t >> 7;
        const int   idx   = t & 127;
        const float start = axis ? x1f : y1f;
        const float sw    = __fdiv_rn(axis ? roi_w : roi_h, 7.0f);
        float w = 0.0f;
#pragma unroll
        for (int k = 0; k < 14; k++) {
            const float off = (float)(k >> 1) + ((k & 1) ? 0.75f : 0.25f);
            const float ss  = __fadd_rn(start, __fmul_rn(off, sw));
            if (ss > -1.0f && ss < 128.0f) {
                const float sc = fminf(fmaxf(ss, 0.0f), 127.0f);
                const int   i0 = (int)floorf(sc);
                const int   i1 = min(i0 + 1, 127);
                const float l  = sc - (float)i0;
                if (i0 == idx) w += 1.0f - l;
                if (i1 == idx) w += l;
            }
        }
        const bool     p    = (w != 0.0f);
        const unsigned m    = __ballot_sync(0xffffffffu, p);
        if (lane == 0) s_warpoff[wrp] = __popc(m);
        __syncthreads();
        int off = 0;
        const int wbase = wrp & 4;           // warps 0-3: rows, 4-7: cols
        for (int wi = wbase; wi < wrp; wi++) off += s_warpoff[wi];
        if (p) {
            const int pos = off + __popc(m & ((1u << lane) - 1));
            if (axis == 0) { s_rows[pos] = idx; s_rw[pos] = w; }
            else           { s_cols[pos] = idx; s_cw[pos] = w; }
        }
        if (lane == 31 && (wrp == 3 || wrp == 7))
            s_cnt[axis] = off + __popc(m);
    }
    __syncthreads();

    // --- Balanced contiguous pixel range for this warp ----------------------
    const int nr  = s_cnt[0], nc = s_cnt[1];
    const int npx = nr * nc;                       // <= 784
    const int q   = s * 8 + wrp;                   // slice 0..31
    const int lo  = (npx * q) >> 5;
    const int hi  = (npx * (q + 1)) >> 5;

    const int ch = lane * 8;
    const __half* base = g_nhwc_h + ((size_t)b * HH * WW) * CC + ch;

    float acc[8] = {0.f, 0.f, 0.f, 0.f, 0.f, 0.f, 0.f, 0.f};
    if (lo < hi) {
        int r = lo / nc;
        int c = lo - r * nc;
        const __half* rowp = base + (size_t)(s_rows[r] * WW) * CC;
        float rwt = s_rw[r];
        int i = lo;

        // main: UB independent pixel loads in flight
        for (; i + UB <= hi; i += UB) {
            float wt[UB];
            uint4 v[UB];
#pragma unroll
            for (int u = 0; u < UB; u++) {
                wt[u] = rwt * s_cw[c];
                v[u]  = *(const uint4*)(rowp + (size_t)s_cols[c] * CC);
                if (++c == nc) {
                    c = 0;
                    if (++r < nr) {
                        rowp = base + (size_t)(s_rows[r] * WW) * CC;
                        rwt  = s_rw[r];
                    }
                }
            }
#pragma unroll
            for (int u = 0; u < UB; u++) {
                const __half2* hp = (const __half2*)&v[u];
#pragma unroll
                for (int k = 0; k < 4; k++) {
                    const float2 f = __half22float2(hp[k]);
                    acc[2 * k]     = fmaf(wt[u], f.x, acc[2 * k]);
                    acc[2 * k + 1] = fmaf(wt[u], f.y, acc[2 * k + 1]);
                }
            }
        }
        // tail
        for (; i < hi; i++) {
            const float wt = rwt * s_cw[c];
            const uint4 v  = *(const uint4*)(rowp + (size_t)s_cols[c] * CC);
            const __half2* hp = (const __half2*)&v;
#pragma unroll
            for (int k = 0; k < 4; k++) {
                const float2 f = __half22float2(hp[k]);
                acc[2 * k]     = fmaf(wt, f.x, acc[2 * k]);
                acc[2 * k + 1] = fmaf(wt, f.y, acc[2 * k + 1]);
            }
            if (++c == nc) {
                c = 0;
                if (++r < nr) {
                    rowp = base + (size_t)(s_rows[r] * WW) * CC;
                    rwt  = s_rw[r];
                }
            }
        }
    }

    float* sp = &s_red[wrp][ch];
#pragma unroll
    for (int k = 0; k < 8; k++) sp[k] = acc[k];
    __syncthreads();

    // combine 8 warp slices -> 256 channel partials (deterministic order)
    float vsum = 0.0f;
#pragma unroll
    for (int sl = 0; sl < 8; sl++) vsum += s_red[sl][t];
    g_part[((size_t)(roi * NSL + s)) * CC + t] = vsum;
}

// ---------------------------------------------------------------------------
// Kernel 3: reduce NSL row-slice partials per ROI, scale by 1/196, write out.
// ---------------------------------------------------------------------------
__global__ __launch_bounds__(64) void roi_reduce_kernel(const float* __restrict__ rois,
                                                        float* __restrict__ out) {
    const int roi = blockIdx.x;
    const int t   = threadIdx.x;   // 0..63
    const float4* p = (const float4*)(g_part + (size_t)roi * NSL * CC);
    float4 r = make_float4(0.f, 0.f, 0.f, 0.f);
#pragma unroll
    for (int sl = 0; sl < NSL; sl++) {
        const float4 a = p[sl * 64 + t];
        r.x += a.x; r.y += a.y; r.z += a.z; r.w += a.w;
    }
    r.x *= (1.0f / 196.0f);
    r.y *= (1.0f / 196.0f);
    r.z *= (1.0f / 196.0f);
    r.w *= (1.0f / 196.0f);
    ((float4*)(out + (size_t)roi * CC))[t] = r;
    if (t == 0)
        out[(size_t)NROI * CC + roi] = rois[roi * 6 + 1];   // gt = rois[:,1]
}

// ---------------------------------------------------------------------------
extern "C" void kernel_launch(void* const* d_in, const int* in_sizes, int n_in,
                              void* d_out, int out_size) {
    const float* feature_map = (const float*)d_in[0];
    const float* rois        = (const float*)d_in[1];
    float* out = (float*)d_out;

    dim3 tg((HH * WW) / 128, CC / 64, BB);     // (128, 4, 4)
    nchw_to_nhwc_h4<<<tg, 256>>>(feature_map);

    roi_partial_kernel<<<dim3(NROI, NSL), 256>>>(rois);
    roi_reduce_kernel<<<NROI, 64>>>(rois, out);
    (void)in_sizes; (void)n_in; (void)out_size;
}

// round 15
// speedup vs baseline: 1.0077x; 1.0077x over previous
#include <cuda_runtime.h>
#include <cuda_fp16.h>

#define HH 128
#define WW 128
#define CC 256
#define BB 4
#define NROI 512
#define NSL 4     // row-slice blocks per ROI
#define UB  6     // pixel batch (loads in flight per thread)

// 32 MB fp16 NHWC scratch + 2 MB partial-sum buffer (static device globals)
__device__ __half g_nhwc_h[(size_t)BB * HH * WW * CC];
__device__ float  g_part[(size_t)NROI * NSL * CC];

// ---------------------------------------------------------------------------
// Kernel 1 (v5): NCHW fp32 -> NHWC fp16 transpose via cp.async.
// Tile: 128 pixels x 64 channels. Phase 1: 8 cp.async (16B) per thread copy
// 64 channel rows (512B each) gmem->smem with zero register pressure; all
// 2048 copies per block in flight at once. 16B chunks are XOR-swizzled by
// ((row>>1)&7) so phase 2 reads spread across all banks.
// Phase 2: lane l reads rows 2l & 2l+1 at one 4-pixel chunk (2x LDS.128,
// bank sharing == data floor), packs half2, stores 128B sector STG
// (lane == channel pair, pixel fixed per store).
// ---------------------------------------------------------------------------
__global__ __launch_bounds__(256) void nchw_to_nhwc_h5(const float* __restrict__ in) {
    __shared__ float smem_f[64 * 128];       // 32 KB raw fp32 tile, swizzled
    const int b    = blockIdx.z;
    const int p0   = blockIdx.x * 128;       // pixel tile base (HW dim)
    const int c0   = blockIdx.y * 64;        // channel tile base
    const int lane = threadIdx.x & 31;
    const int wrp  = threadIdx.x >> 5;       // 0..7

    const float* src = in + (size_t)b * CC * (HH * WW) + p0;
    const unsigned smem_u32 = (unsigned)__cvta_generic_to_shared(smem_f);

    // Phase 1: async copy. warp w, step k -> channel row w*8+k; lane l copies
    // original chunk l (bytes 16l..16l+15) to swizzled chunk l ^ ((row>>1)&7).
#pragma unroll
    for (int k = 0; k < 8; k++) {
        const int row   = wrp * 8 + k;                     // 0..63
        const int chunk = lane ^ ((row >> 1) & 7);
        const unsigned dst = smem_u32 + (unsigned)((row * 128 + chunk * 4) * 4);
        const float* gsrc = src + (size_t)(c0 + row) * (HH * WW) + lane * 4;
        asm volatile("cp.async.cg.shared.global [%0], [%1], 16;\n"
                     :: "r"(dst), "l"(gsrc));
    }
    asm volatile("cp.async.commit_group;\n" ::: "memory");
    asm volatile("cp.async.wait_group 0;\n" ::: "memory");
    __syncthreads();

    // Phase 2: pack + write. warp w covers pixel chunks 4w..4w+3.
    unsigned int* dstbase = (unsigned int*)g_nhwc_h
                          + ((size_t)b * (HH * WW)) * (CC / 2) + (c0 >> 1);
    const int sw = lane & 7;                 // == ((2*lane)>>1)&7 == ((2*lane+1)>>1)&7
#pragma unroll
    for (int cc = 0; cc < 4; cc++) {
        const int c = wrp * 4 + cc;          // pixel chunk 0..31 (pixels 4c..4c+3)
        const float4 fa = *(const float4*)&smem_f[(2 * lane)     * 128 + ((c ^ sw) * 4)];
        const float4 fb = *(const float4*)&smem_f[(2 * lane + 1) * 128 + ((c ^ sw) * 4)];
        const __half2 h0 = __floats2half2_rn(fa.x, fb.x);
        const __half2 h1 = __floats2half2_rn(fa.y, fb.y);
        const __half2 h2 = __floats2half2_rn(fa.z, fb.z);
        const __half2 h3 = __floats2half2_rn(fa.w, fb.w);
        dstbase[(size_t)(p0 + 4 * c + 0) * (CC / 2) + lane] = *(const unsigned int*)&h0;
        dstbase[(size_t)(p0 + 4 * c + 1) * (CC / 2) + lane] = *(const unsigned int*)&h1;
        dstbase[(size_t)(p0 + 4 * c + 2) * (CC / 2) + lane] = *(const unsigned int*)&h2;
        dstbase[(size_t)(p0 + 4 * c + 3) * (CC / 2) + lane] = *(const unsigned int*)&h3;
    }
}

// ---------------------------------------------------------------------------
// Kernel 2: block (roi, s). Footprint (nr x nc) flattened to npx pixels; 32
// contiguous balanced ranges over 4 blocks x 8 warps. Lanes carry 8 channels
// (uint4). UB independent loads in flight; 64-reg budget.
// (unchanged from R12: measured ~25us incl. reduce)
// ---------------------------------------------------------------------------
__global__ __launch_bounds__(256, 4) void roi_partial_kernel(const float* __restrict__ rois) {
    const int roi  = blockIdx.x;
    const int s    = blockIdx.y;     // 0..3
    const int t    = threadIdx.x;
    const int lane = t & 31;
    const int wrp  = t >> 5;         // 0..7

    __shared__ int   s_rows[32];
    __shared__ float s_rw[32];
    __shared__ int   s_cols[32];
    __shared__ float s_cw[32];
    __shared__ int   s_cnt[2];
    __shared__ int   s_warpoff[8];
    __shared__ float s_red[8][CC];   // 8 KB

    // --- ROI params (every thread; same FP ops as reference) ----------------
    const float* R = rois + roi * 6;
    const int   b   = (int)R[0];
    const float cx  = R[2], cy = R[3], rw_ = R[4], rh_ = R[5];
    const float x1f = __half2float(__float2half_rn((cx - 0.5f * rw_) * 128.0f));
    const float y1f = __half2float(__float2half_rn((cy - 0.5f * rh_) * 128.0f));
    const float x2f = __half2float(__float2half_rn((cx + 0.5f * rw_) * 128.0f));
    const float y2f = __half2float(__float2half_rn((cy + 0.5f * rh_) * 128.0f));
    const float roi_w = fmaxf(x2f - x1f, 1.0f);
    const float roi_h = fmaxf(y2f - y1f, 1.0f);

    // --- Per-thread axis weight: threads 0-127 -> rows, 128-255 -> cols -----
    {
        const int   axis  = t >> 7;
        const int   idx   = t & 127;
        const float start = axis ? x1f : y1f;
        const float sw    = __fdiv_rn(axis ? roi_w : roi_h, 7.0f);
        float w = 0.0f;
#pragma unroll
        for (int k = 0; k < 14; k++) {
            const float off = (float)(k >> 1) + ((k & 1) ? 0.75f : 0.25f);
            const float ss  = __fadd_rn(start, __fmul_rn(off, sw));
            if (ss > -1.0f && ss < 128.0f) {
                const float sc = fminf(fmaxf(ss, 0.0f), 127.0f);
                const int   i0 = (int)floorf(sc);
                const int   i1 = min(i0 + 1, 127);
                const float l  = sc - (float)i0;
                if (i0 == idx) w += 1.0f - l;
                if (i1 == idx) w += l;
            }
        }
        const bool     p    = (w != 0.0f);
        const unsigned m    = __ballot_sync(0xffffffffu, p);
        if (lane == 0) s_warpoff[wrp] = __popc(m);
        __syncthreads();
        int off = 0;
        const int wbase = wrp & 4;           // warps 0-3: rows, 4-7: cols
        for (int wi = wbase; wi < wrp; wi++) off += s_warpoff[wi];
        if (p) {
            const int pos = off + __popc(m & ((1u << lane) - 1));
            if (axis == 0) { s_rows[pos] = idx; s_rw[pos] = w; }
            else           { s_cols[pos] = idx; s_cw[pos] = w; }
        }
        if (lane == 31 && (wrp == 3 || wrp == 7))
            s_cnt[axis] = off + __popc(m);
    }
    __syncthreads();

    // --- Balanced contiguous pixel range for this warp ----------------------
    const int nr  = s_cnt[0], nc = s_cnt[1];
    const int npx = nr * nc;                       // <= 784
    const int q   = s * 8 + wrp;                   // slice 0..31
    const int lo  = (npx * q) >> 5;
    const int hi  = (npx * (q + 1)) >> 5;

    const int ch = lane * 8;
    const __half* base = g_nhwc_h + ((size_t)b * HH * WW) * CC + ch;

    float acc[8] = {0.f, 0.f, 0.f, 0.f, 0.f, 0.f, 0.f, 0.f};
    if (lo < hi) {
        int r = lo / nc;
        int c = lo - r * nc;
        const __half* rowp = base + (size_t)(s_rows[r] * WW) * CC;
        float rwt = s_rw[r];
        int i = lo;

        // main: UB independent pixel loads in flight
        for (; i + UB <= hi; i += UB) {
            float wt[UB];
            uint4 v[UB];
#pragma unroll
            for (int u = 0; u < UB; u++) {
                wt[u] = rwt * s_cw[c];
                v[u]  = *(const uint4*)(rowp + (size_t)s_cols[c] * CC);
                if (++c == nc) {
                    c = 0;
                    if (++r < nr) {
                        rowp = base + (size_t)(s_rows[r] * WW) * CC;
                        rwt  = s_rw[r];
                    }
                }
            }
#pragma unroll
            for (int u = 0; u < UB; u++) {
                const __half2* hp = (const __half2*)&v[u];
#pragma unroll
                for (int k = 0; k < 4; k++) {
                    const float2 f = __half22float2(hp[k]);
                    acc[2 * k]     = fmaf(wt[u], f.x, acc[2 * k]);
                    acc[2 * k + 1] = fmaf(wt[u], f.y, acc[2 * k + 1]);
                }
            }
        }
        // tail
        for (; i < hi; i++) {
            const float wt = rwt * s_cw[c];
            const uint4 v  = *(const uint4*)(rowp + (size_t)s_cols[c] * CC);
            const __half2* hp = (const __half2*)&v;
#pragma unroll
            for (int k = 0; k < 4; k++) {
                const float2 f = __half22float2(hp[k]);
                acc[2 * k]     = fmaf(wt, f.x, acc[2 * k]);
                acc[2 * k + 1] = fmaf(wt, f.y, acc[2 * k + 1]);
            }
            if (++c == nc) {
                c = 0;
                if (++r < nr) {
                    rowp = base + (size_t)(s_rows[r] * WW) * CC;
                    rwt  = s_rw[r];
                }
            }
        }
    }

    float* sp = &s_red[wrp][ch];
#pragma unroll
    for (int k = 0; k < 8; k++) sp[k] = acc[k];
    __syncthreads();

    // combine 8 warp slices -> 256 channel partials (deterministic order)
    float vsum = 0.0f;
#pragma unroll
    for (int sl = 0; sl < 8; sl++) vsum += s_red[sl][t];
    g_part[((size_t)(roi * NSL + s)) * CC + t] = vsum;
}

// ---------------------------------------------------------------------------
// Kernel 3: reduce NSL row-slice partials per ROI, scale by 1/196, write out.
// ---------------------------------------------------------------------------
__global__ __launch_bounds__(64) void roi_reduce_kernel(const float* __restrict__ rois,
                                                        float* __restrict__ out) {
    const int roi = blockIdx.x;
    const int t   = threadIdx.x;   // 0..63
    const float4* p = (const float4*)(g_part + (size_t)roi * NSL * CC);
    float4 r = make_float4(0.f, 0.f, 0.f, 0.f);
#pragma unroll
    for (int sl = 0; sl < NSL; sl++) {
        const float4 a = p[sl * 64 + t];
        r.x += a.x; r.y += a.y; r.z += a.z; r.w += a.w;
    }
    r.x *= (1.0f / 196.0f);
    r.y *= (1.0f / 196.0f);
    r.z *= (1.0f / 196.0f);
    r.w *= (1.0f / 196.0f);
    ((float4*)(out + (size_t)roi * CC))[t] = r;
    if (t == 0)
        out[(size_t)NROI * CC + roi] = rois[roi * 6 + 1];   // gt = rois[:,1]
}

// ---------------------------------------------------------------------------
extern "C" void kernel_launch(void* const* d_in, const int* in_sizes, int n_in,
                              void* d_out, int out_size) {
    const float* feature_map = (const float*)d_in[0];
    const float* rois        = (const float*)d_in[1];
    float* out = (float*)d_out;

    dim3 tg((HH * WW) / 128, CC / 64, BB);     // (128, 4, 4)
    nchw_to_nhwc_h5<<<tg, 256>>>(feature_map);

    roi_partial_kernel<<<dim3(NROI, NSL), 256>>>(rois);
    roi_reduce_kernel<<<NROI, 64>>>(rois, out);
    (void)in_sizes; (void)n_in; (void)out_size;
}